// round 1
// baseline (speedup 1.0000x reference)
#include <cuda_runtime.h>
#include <math.h>

// ---------------- problem constants ----------------
#define V_   32000
#define D_   1024
#define H_   16
#define KVH_ 4
#define HD_  64
#define F_   4096
#define L_   2
#define B_   2
#define S_   2048
#define T_   (B_*S_)          // 4096 tokens
#define REP_ (H_/KVH_)        // 4
#define EPS_ 1e-5f
#define SCALE_ 0.125f         // 1/sqrt(64)

// ---------------- scratch (device globals, no allocation) ----------------
__device__ float g_x  [T_*D_];          // residual stream
__device__ float g_n  [T_*D_];          // normalized activations
__device__ float g_q  [T_*D_];
__device__ float g_k  [T_*KVH_*HD_];
__device__ float g_v  [T_*KVH_*HD_];
__device__ float g_ctx[T_*D_];
__device__ float g_gate[T_*F_];
__device__ float g_up  [T_*F_];
__device__ int   g_is64;

// ---------------- int32/int64 index detection ----------------
// If the index buffer is int64 (little-endian, values < 32000), every odd
// 32-bit word is zero. If int32, odd words are real tokens (not all zero).
__global__ void detect_idx_kernel(const int* idx) {
    __shared__ int ok;
    if (threadIdx.x == 0) ok = 1;
    __syncthreads();
    int bad = 0;
    for (int i = threadIdx.x; i < T_/2; i += blockDim.x)
        if (idx[2*i + 1] != 0) bad = 1;
    if (bad) atomicAnd(&ok, 0);
    __syncthreads();
    if (threadIdx.x == 0) g_is64 = ok;
}

// ---------------- embedding gather ----------------
__global__ void embed_kernel(const void* idx, const float* __restrict__ emb) {
    int t = blockIdx.x;
    int tok = g_is64 ? (int)((const long long*)idx)[t] : ((const int*)idx)[t];
    const float4* src = (const float4*)(emb + (size_t)tok * D_);
    float4* dst = (float4*)(g_x + (size_t)t * D_);
    dst[threadIdx.x] = src[threadIdx.x];   // 256 threads * float4 = 1024 floats
}

// ---------------- RMSNorm: out = x * rsqrt(mean(x^2)+eps) * w ----------------
__global__ void rmsnorm_kernel(const float* __restrict__ x,
                               const float* __restrict__ w,
                               float* __restrict__ out) {
    int t = blockIdx.x;
    __shared__ float red[8];
    float4 v = ((const float4*)(x + (size_t)t * D_))[threadIdx.x];
    float ss = v.x*v.x + v.y*v.y + v.z*v.z + v.w*v.w;
    #pragma unroll
    for (int o = 16; o > 0; o >>= 1) ss += __shfl_xor_sync(0xffffffffu, ss, o);
    if ((threadIdx.x & 31) == 0) red[threadIdx.x >> 5] = ss;
    __syncthreads();
    if (threadIdx.x < 8) {
        float s = red[threadIdx.x];
        #pragma unroll
        for (int o = 4; o > 0; o >>= 1) s += __shfl_xor_sync(0xffu, s, o);
        if (threadIdx.x == 0) red[0] = s;
    }
    __syncthreads();
    float inv = rsqrtf(red[0] * (1.0f / D_) + EPS_);
    float4 wv = ((const float4*)w)[threadIdx.x];
    float4 o4;
    o4.x = v.x * inv * wv.x; o4.y = v.y * inv * wv.y;
    o4.z = v.z * inv * wv.z; o4.w = v.w * inv * wv.w;
    ((float4*)(out + (size_t)t * D_))[threadIdx.x] = o4;
}

// ---------------- RoPE (in place): pairs (d, d+32) per head ----------------
__global__ void rope_kernel(float* __restrict__ x, int nheads) {
    int t   = blockIdx.x;
    int pos = t % S_;
    int j   = threadIdx.x & 31;        // 0..31
    int h   = threadIdx.x >> 5;        // head
    float invf = powf(500000.0f, -(float)(2 * j) / (float)HD_);
    float ang = (float)pos * invf;
    float s, c;
    sincosf(ang, &s, &c);
    float* p = x + (size_t)t * nheads * HD_ + h * HD_;
    float a = p[j], b = p[j + 32];
    p[j]      = a * c - b * s;
    p[j + 32] = b * c + a * s;
}

// ---------------- Flash attention, 64x64 tiles, fp32 ----------------
#define BQ  64
#define BKV 64
struct FlashSmem {
    float Qs[64][68];
    float Ks[64][68];
    float Ss[64][68];
    float Vs[64][68];
    float m[64], l[64], resc[64];
};

__global__ void __launch_bounds__(256)
flash_kernel(const float* __restrict__ q, const float* __restrict__ k,
             const float* __restrict__ v, float* __restrict__ ctx) {
    extern __shared__ char smraw[];
    FlashSmem& sm = *(FlashSmem*)smraw;

    int q0  = blockIdx.x * BQ;
    int h   = blockIdx.y;
    int b   = blockIdx.z;
    int kvh = h / REP_;
    int tid = threadIdx.x;
    int tx  = tid & 15;      // 0..15 -> 4 output cols
    int ty  = tid >> 4;      // 0..15 -> 4 output rows

    // load Q tile (64 rows x 64 floats)
    for (int i = tid; i < BQ * 16; i += 256) {
        int r = i >> 4, c4 = (i & 15) * 4;
        *(float4*)&sm.Qs[r][c4] =
            *(const float4*)(q + ((size_t)(b * S_ + q0 + r) * D_ + h * HD_ + c4));
    }
    if (tid < 64) { sm.m[tid] = -INFINITY; sm.l[tid] = 0.f; }
    float o[4][4] = {};
    __syncthreads();

    int ntiles = q0 / BKV + 1;
    for (int tI = 0; tI < ntiles; tI++) {
        int kv0 = tI * BKV;
        // load K/V tiles
        for (int i = tid; i < BKV * 16; i += 256) {
            int r = i >> 4, c4 = (i & 15) * 4;
            size_t base = (size_t)(b * S_ + kv0 + r) * (KVH_ * HD_) + kvh * HD_ + c4;
            *(float4*)&sm.Ks[r][c4] = *(const float4*)(k + base);
            *(float4*)&sm.Vs[r][c4] = *(const float4*)(v + base);
        }
        __syncthreads();

        // S = Q K^T
        float s[4][4] = {};
        #pragma unroll
        for (int kk = 0; kk < HD_; kk++) {
            float a[4], bb[4];
            #pragma unroll
            for (int i = 0; i < 4; i++) a[i]  = sm.Qs[ty*4 + i][kk];
            #pragma unroll
            for (int j = 0; j < 4; j++) bb[j] = sm.Ks[tx*4 + j][kk];
            #pragma unroll
            for (int i = 0; i < 4; i++)
                #pragma unroll
                for (int j = 0; j < 4; j++) s[i][j] += a[i] * bb[j];
        }
        bool diag = (kv0 == q0);   // only the diagonal tile needs masking
        #pragma unroll
        for (int i = 0; i < 4; i++)
            #pragma unroll
            for (int j = 0; j < 4; j++) {
                float val = s[i][j] * SCALE_;
                if (diag && (kv0 + tx*4 + j) > (q0 + ty*4 + i)) val = -INFINITY;
                sm.Ss[ty*4 + i][tx*4 + j] = val;
            }
        __syncthreads();

        // streaming softmax: each warp owns 8 rows
        {
            int w = tid >> 5, lane = tid & 31;
            for (int rr = 0; rr < 8; rr++) {
                int r = w * 8 + rr;
                float s0 = sm.Ss[r][lane], s1 = sm.Ss[r][lane + 32];
                float mx = fmaxf(s0, s1);
                #pragma unroll
                for (int o_ = 16; o_ > 0; o_ >>= 1)
                    mx = fmaxf(mx, __shfl_xor_sync(0xffffffffu, mx, o_));
                float mold = sm.m[r];
                float mnew = fmaxf(mold, mx);
                float p0 = expf(s0 - mnew), p1 = expf(s1 - mnew);
                sm.Ss[r][lane] = p0; sm.Ss[r][lane + 32] = p1;
                float sum = p0 + p1;
                #pragma unroll
                for (int o_ = 16; o_ > 0; o_ >>= 1)
                    sum += __shfl_xor_sync(0xffffffffu, sum, o_);
                if (lane == 0) {
                    float f = expf(mold - mnew);   // mold = -inf -> 0
                    sm.resc[r] = f;
                    sm.l[r] = sm.l[r] * f + sum;
                    sm.m[r] = mnew;
                }
            }
        }
        __syncthreads();

        // O = O*resc + P V
        float f4[4];
        #pragma unroll
        for (int i = 0; i < 4; i++) f4[i] = sm.resc[ty*4 + i];
        #pragma unroll
        for (int i = 0; i < 4; i++)
            #pragma unroll
            for (int j = 0; j < 4; j++) o[i][j] *= f4[i];
        #pragma unroll
        for (int kk = 0; kk < BKV; kk++) {
            float p[4];
            #pragma unroll
            for (int i = 0; i < 4; i++) p[i] = sm.Ss[ty*4 + i][kk];
            float4 vv = *(const float4*)&sm.Vs[kk][tx*4];
            #pragma unroll
            for (int i = 0; i < 4; i++) {
                o[i][0] += p[i] * vv.x; o[i][1] += p[i] * vv.y;
                o[i][2] += p[i] * vv.z; o[i][3] += p[i] * vv.w;
            }
        }
        __syncthreads();
    }

    // normalize + write ctx
    #pragma unroll
    for (int i = 0; i < 4; i++) {
        int r = ty*4 + i;
        float invl = 1.0f / sm.l[r];
        float4 ov;
        ov.x = o[i][0]*invl; ov.y = o[i][1]*invl;
        ov.z = o[i][2]*invl; ov.w = o[i][3]*invl;
        *(float4*)(ctx + ((size_t)(b * S_ + q0 + r) * D_ + h * HD_ + tx*4)) = ov;
    }
}

// ---------------- generic SGEMM: C = A[MxK] @ B[KxN] (+ Res) ----------------
// BM=128 BN=128 BK=8, 256 threads, 8x8 per thread. All dims divisible.
__global__ void __launch_bounds__(256)
sgemm_kernel(const float* __restrict__ A, const float* __restrict__ B,
             const float* __restrict__ Res, float* __restrict__ C,
             int M, int N, int K) {
    const int BM = 128, BN = 128, BK = 8, TM = 8, TN = 8;
    __shared__ float As[BK][BM];
    __shared__ float Bs[BK][BN];
    int bx = blockIdx.x, by = blockIdx.y;
    int tid = threadIdx.x;
    int tC = tid & 15;          // col group
    int tR = tid >> 4;          // row group

    const float* Ab = A + (size_t)by * BM * K;
    const float* Bb = B + (size_t)bx * BN;

    int arow = tid >> 1, ac4 = (tid & 1) * 4;
    int brow = tid >> 5, bc4 = (tid & 31) * 4;

    float acc[TM][TN] = {};
    for (int k0 = 0; k0 < K; k0 += BK) {
        float4 a = *(const float4*)(Ab + (size_t)arow * K + k0 + ac4);
        As[ac4 + 0][arow] = a.x; As[ac4 + 1][arow] = a.y;
        As[ac4 + 2][arow] = a.z; As[ac4 + 3][arow] = a.w;
        *(float4*)&Bs[brow][bc4] =
            *(const float4*)(Bb + (size_t)(k0 + brow) * N + bc4);
        __syncthreads();
        #pragma unroll
        for (int k = 0; k < BK; k++) {
            float rm[TM], rn[TN];
            #pragma unroll
            for (int i = 0; i < TM; i++) rm[i] = As[k][tR * TM + i];
            #pragma unroll
            for (int j = 0; j < TN; j++) rn[j] = Bs[k][tC * TN + j];
            #pragma unroll
            for (int i = 0; i < TM; i++)
                #pragma unroll
                for (int j = 0; j < TN; j++) acc[i][j] += rm[i] * rn[j];
        }
        __syncthreads();
    }
    #pragma unroll
    for (int i = 0; i < TM; i++) {
        size_t row = (size_t)by * BM + tR * TM + i;
        #pragma unroll
        for (int j = 0; j < TN; j += 4) {
            size_t col = (size_t)bx * BN + tC * TN + j;
            float4 o;
            o.x = acc[i][j]; o.y = acc[i][j+1]; o.z = acc[i][j+2]; o.w = acc[i][j+3];
            if (Res) {
                float4 r = *(const float4*)(Res + row * N + col);
                o.x += r.x; o.y += r.y; o.z += r.z; o.w += r.w;
            }
            *(float4*)(C + row * N + col) = o;
        }
    }
}

// ---------------- SwiGLU elementwise: g = silu(g) * u ----------------
__global__ void silu_mult_kernel(float* __restrict__ g, const float* __restrict__ u) {
    int i = blockIdx.x * blockDim.x + threadIdx.x;   // over float4 elements
    float4 gv = ((const float4*)g)[i];
    float4 uv = ((const float4*)u)[i];
    gv.x = gv.x / (1.f + expf(-gv.x)) * uv.x;
    gv.y = gv.y / (1.f + expf(-gv.y)) * uv.y;
    gv.z = gv.z / (1.f + expf(-gv.z)) * uv.z;
    gv.w = gv.w / (1.f + expf(-gv.w)) * uv.w;
    ((float4*)g)[i] = gv;
}

// ---------------- host orchestration ----------------
static inline void run_sgemm(const float* A, const float* B, const float* Res,
                             float* C, int M, int N, int K) {
    dim3 grid(N / 128, M / 128);
    sgemm_kernel<<<grid, 256>>>(A, B, Res, C, M, N, K);
}

extern "C" void kernel_launch(void* const* d_in, const int* in_sizes, int n_in,
                              void* d_out, int out_size) {
    const void*  idx    = d_in[0];
    const float* emb    = (const float*)d_in[1];
    const float* wq     = (const float*)d_in[2];
    const float* wk     = (const float*)d_in[3];
    const float* wv     = (const float*)d_in[4];
    const float* wo     = (const float*)d_in[5];
    const float* wgate  = (const float*)d_in[6];
    const float* wup    = (const float*)d_in[7];
    const float* wdown  = (const float*)d_in[8];
    const float* na     = (const float*)d_in[9];
    const float* nf     = (const float*)d_in[10];
    const float* nfin   = (const float*)d_in[11];
    const float* wout   = (const float*)d_in[12];

    float *x, *n, *q, *k, *v, *ctx, *gate, *up;
    cudaGetSymbolAddress((void**)&x,    g_x);
    cudaGetSymbolAddress((void**)&n,    g_n);
    cudaGetSymbolAddress((void**)&q,    g_q);
    cudaGetSymbolAddress((void**)&k,    g_k);
    cudaGetSymbolAddress((void**)&v,    g_v);
    cudaGetSymbolAddress((void**)&ctx,  g_ctx);
    cudaGetSymbolAddress((void**)&gate, g_gate);
    cudaGetSymbolAddress((void**)&up,   g_up);

    static const int FLASH_SMEM = sizeof(FlashSmem);
    cudaFuncSetAttribute(flash_kernel,
                         cudaFuncAttributeMaxDynamicSharedMemorySize, FLASH_SMEM);

    detect_idx_kernel<<<1, 256>>>((const int*)idx);
    embed_kernel<<<T_, 256>>>(idx, emb);

    for (int l = 0; l < L_; l++) {
        rmsnorm_kernel<<<T_, 256>>>(x, na + (size_t)l * D_, n);
        run_sgemm(n, wq + (size_t)l * D_ * D_,          nullptr, q, T_, D_,        D_);
        run_sgemm(n, wk + (size_t)l * D_ * KVH_ * HD_,  nullptr, k, T_, KVH_*HD_,  D_);
        run_sgemm(n, wv + (size_t)l * D_ * KVH_ * HD_,  nullptr, v, T_, KVH_*HD_,  D_);
        rope_kernel<<<T_, H_ * 32>>>(q, H_);
        rope_kernel<<<T_, KVH_ * 32>>>(k, KVH_);
        flash_kernel<<<dim3(S_ / BQ, H_, B_), 256, FLASH_SMEM>>>(q, k, v, ctx);
        run_sgemm(ctx, wo + (size_t)l * D_ * D_, x, x, T_, D_, D_);   // x += ctx@wo
        rmsnorm_kernel<<<T_, 256>>>(x, nf + (size_t)l * D_, n);
        run_sgemm(n, wgate + (size_t)l * D_ * F_, nullptr, gate, T_, F_, D_);
        run_sgemm(n, wup   + (size_t)l * D_ * F_, nullptr, up,   T_, F_, D_);
        silu_mult_kernel<<<(T_ * F_ / 4) / 256, 256>>>(gate, up);
        run_sgemm(gate, wdown + (size_t)l * F_ * D_, x, x, T_, D_, F_); // x += h@wdown
    }

    rmsnorm_kernel<<<T_, 256>>>(x, nfin, n);
    run_sgemm(n, wout, nullptr, (float*)d_out, T_, V_, D_);
}

// round 2
// speedup vs baseline: 2.0505x; 2.0505x over previous
#include <cuda_runtime.h>
#include <cuda_bf16.h>
#include <math.h>
#include <stdint.h>

// ---------------- problem constants ----------------
#define V_   32000
#define D_   1024
#define H_   16
#define KVH_ 4
#define HD_  64
#define F_   4096
#define L_   2
#define B_   2
#define S_   2048
#define T_   (B_*S_)          // 4096 tokens
#define REP_ (H_/KVH_)        // 4
#define EPS_ 1e-5f
#define SCALE_ 0.125f         // 1/sqrt(64)

typedef __nv_bfloat16 bf16;

// ---------------- scratch (device globals, no allocation) ----------------
__device__ float g_x  [T_*D_];
__device__ float g_n  [T_*D_];
__device__ float g_q  [T_*D_];
__device__ float g_k  [T_*KVH_*HD_];
__device__ float g_v  [T_*KVH_*HD_];
__device__ float g_ctx[T_*D_];
__device__ float g_gate[T_*F_];
__device__ float g_up  [T_*F_];
__device__ int   g_is64;

// bf16 hi/lo planes for all weights
__device__ bf16 g_wq_h [L_*D_*D_],        g_wq_l [L_*D_*D_];
__device__ bf16 g_wk_h [L_*D_*KVH_*HD_],  g_wk_l [L_*D_*KVH_*HD_];
__device__ bf16 g_wv_h [L_*D_*KVH_*HD_],  g_wv_l [L_*D_*KVH_*HD_];
__device__ bf16 g_wo_h [L_*D_*D_],        g_wo_l [L_*D_*D_];
__device__ bf16 g_wg_h [L_*D_*F_],        g_wg_l [L_*D_*F_];
__device__ bf16 g_wu_h [L_*D_*F_],        g_wu_l [L_*D_*F_];
__device__ bf16 g_wd_h [L_*F_*D_],        g_wd_l [L_*F_*D_];
__device__ bf16 g_wout_h[D_*V_],          g_wout_l[D_*V_];

// ---------------- helpers ----------------
__device__ __forceinline__ uint32_t pack2(bf16 a, bf16 b) {
    __nv_bfloat162 t = __halves2bfloat162(a, b);
    return *reinterpret_cast<uint32_t*>(&t);
}

// ---------------- fp32 -> bf16 hi/lo split ----------------
__global__ void split_kernel(const float* __restrict__ in,
                             bf16* __restrict__ hi, bf16* __restrict__ lo, int n4) {
    int i = blockIdx.x * blockDim.x + threadIdx.x;
    if (i >= n4) return;
    float4 v = ((const float4*)in)[i];
    float vv[4] = {v.x, v.y, v.z, v.w};
    bf16 h[4], l[4];
    #pragma unroll
    for (int j = 0; j < 4; j++) {
        h[j] = __float2bfloat16(vv[j]);
        l[j] = __float2bfloat16(vv[j] - __bfloat162float(h[j]));
    }
    ((uint2*)hi)[i] = make_uint2(pack2(h[0],h[1]), pack2(h[2],h[3]));
    ((uint2*)lo)[i] = make_uint2(pack2(l[0],l[1]), pack2(l[2],l[3]));
}

// ---------------- int32/int64 index detection ----------------
__global__ void detect_idx_kernel(const int* idx) {
    __shared__ int ok;
    if (threadIdx.x == 0) ok = 1;
    __syncthreads();
    int bad = 0;
    for (int i = threadIdx.x; i < T_/2; i += blockDim.x)
        if (idx[2*i + 1] != 0) bad = 1;
    if (bad) atomicAnd(&ok, 0);
    __syncthreads();
    if (threadIdx.x == 0) g_is64 = ok;
}

// ---------------- embedding gather ----------------
__global__ void embed_kernel(const void* idx, const float* __restrict__ emb) {
    int t = blockIdx.x;
    int tok = g_is64 ? (int)((const long long*)idx)[t] : ((const int*)idx)[t];
    const float4* src = (const float4*)(emb + (size_t)tok * D_);
    float4* dst = (float4*)(g_x + (size_t)t * D_);
    dst[threadIdx.x] = src[threadIdx.x];
}

// ---------------- RMSNorm ----------------
__global__ void rmsnorm_kernel(const float* __restrict__ x,
                               const float* __restrict__ w,
                               float* __restrict__ out) {
    int t = blockIdx.x;
    __shared__ float red[8];
    float4 v = ((const float4*)(x + (size_t)t * D_))[threadIdx.x];
    float ss = v.x*v.x + v.y*v.y + v.z*v.z + v.w*v.w;
    #pragma unroll
    for (int o = 16; o > 0; o >>= 1) ss += __shfl_xor_sync(0xffffffffu, ss, o);
    if ((threadIdx.x & 31) == 0) red[threadIdx.x >> 5] = ss;
    __syncthreads();
    if (threadIdx.x < 8) {
        float s = red[threadIdx.x];
        #pragma unroll
        for (int o = 4; o > 0; o >>= 1) s += __shfl_xor_sync(0xffu, s, o);
        if (threadIdx.x == 0) red[0] = s;
    }
    __syncthreads();
    float inv = rsqrtf(red[0] * (1.0f / D_) + EPS_);
    float4 wv = ((const float4*)w)[threadIdx.x];
    float4 o4;
    o4.x = v.x * inv * wv.x; o4.y = v.y * inv * wv.y;
    o4.z = v.z * inv * wv.z; o4.w = v.w * inv * wv.w;
    ((float4*)(out + (size_t)t * D_))[threadIdx.x] = o4;
}

// ---------------- RoPE ----------------
__global__ void rope_kernel(float* __restrict__ x, int nheads) {
    int t   = blockIdx.x;
    int pos = t % S_;
    int j   = threadIdx.x & 31;
    int h   = threadIdx.x >> 5;
    float invf = powf(500000.0f, -(float)(2 * j) / (float)HD_);
    float ang = (float)pos * invf;
    float s, c;
    sincosf(ang, &s, &c);
    float* p = x + (size_t)t * nheads * HD_ + h * HD_;
    float a = p[j], b = p[j + 32];
    p[j]      = a * c - b * s;
    p[j + 32] = b * c + a * s;
}

// ---------------- Flash attention, 64x64 tiles, fp32 ----------------
#define BQ  64
#define BKV 64
struct FlashSmem {
    float Qs[64][68];
    float Ks[64][68];
    float Ss[64][68];
    float Vs[64][68];
    float m[64], l[64], resc[64];
};

__global__ void __launch_bounds__(256)
flash_kernel(const float* __restrict__ q, const float* __restrict__ k,
             const float* __restrict__ v, float* __restrict__ ctx) {
    extern __shared__ char smraw[];
    FlashSmem& sm = *(FlashSmem*)smraw;

    int q0  = blockIdx.x * BQ;
    int h   = blockIdx.y;
    int b   = blockIdx.z;
    int kvh = h / REP_;
    int tid = threadIdx.x;
    int tx  = tid & 15;
    int ty  = tid >> 4;

    for (int i = tid; i < BQ * 16; i += 256) {
        int r = i >> 4, c4 = (i & 15) * 4;
        *(float4*)&sm.Qs[r][c4] =
            *(const float4*)(q + ((size_t)(b * S_ + q0 + r) * D_ + h * HD_ + c4));
    }
    if (tid < 64) { sm.m[tid] = -INFINITY; sm.l[tid] = 0.f; }
    float o[4][4] = {};
    __syncthreads();

    int ntiles = q0 / BKV + 1;
    for (int tI = 0; tI < ntiles; tI++) {
        int kv0 = tI * BKV;
        for (int i = tid; i < BKV * 16; i += 256) {
            int r = i >> 4, c4 = (i & 15) * 4;
            size_t base = (size_t)(b * S_ + kv0 + r) * (KVH_ * HD_) + kvh * HD_ + c4;
            *(float4*)&sm.Ks[r][c4] = *(const float4*)(k + base);
            *(float4*)&sm.Vs[r][c4] = *(const float4*)(v + base);
        }
        __syncthreads();

        float s[4][4] = {};
        #pragma unroll
        for (int kk = 0; kk < HD_; kk++) {
            float a[4], bb[4];
            #pragma unroll
            for (int i = 0; i < 4; i++) a[i]  = sm.Qs[ty*4 + i][kk];
            #pragma unroll
            for (int j = 0; j < 4; j++) bb[j] = sm.Ks[tx*4 + j][kk];
            #pragma unroll
            for (int i = 0; i < 4; i++)
                #pragma unroll
                for (int j = 0; j < 4; j++) s[i][j] += a[i] * bb[j];
        }
        bool diag = (kv0 == q0);
        #pragma unroll
        for (int i = 0; i < 4; i++)
            #pragma unroll
            for (int j = 0; j < 4; j++) {
                float val = s[i][j] * SCALE_;
                if (diag && (kv0 + tx*4 + j) > (q0 + ty*4 + i)) val = -INFINITY;
                sm.Ss[ty*4 + i][tx*4 + j] = val;
            }
        __syncthreads();

        {
            int w = tid >> 5, lane = tid & 31;
            for (int rr = 0; rr < 8; rr++) {
                int r = w * 8 + rr;
                float s0 = sm.Ss[r][lane], s1 = sm.Ss[r][lane + 32];
                float mx = fmaxf(s0, s1);
                #pragma unroll
                for (int o_ = 16; o_ > 0; o_ >>= 1)
                    mx = fmaxf(mx, __shfl_xor_sync(0xffffffffu, mx, o_));
                float mold = sm.m[r];
                float mnew = fmaxf(mold, mx);
                float p0 = expf(s0 - mnew), p1 = expf(s1 - mnew);
                sm.Ss[r][lane] = p0; sm.Ss[r][lane + 32] = p1;
                float sum = p0 + p1;
                #pragma unroll
                for (int o_ = 16; o_ > 0; o_ >>= 1)
                    sum += __shfl_xor_sync(0xffffffffu, sum, o_);
                if (lane == 0) {
                    float f = expf(mold - mnew);
                    sm.resc[r] = f;
                    sm.l[r] = sm.l[r] * f + sum;
                    sm.m[r] = mnew;
                }
            }
        }
        __syncthreads();

        float f4[4];
        #pragma unroll
        for (int i = 0; i < 4; i++) f4[i] = sm.resc[ty*4 + i];
        #pragma unroll
        for (int i = 0; i < 4; i++)
            #pragma unroll
            for (int j = 0; j < 4; j++) o[i][j] *= f4[i];
        #pragma unroll
        for (int kk = 0; kk < BKV; kk++) {
            float p[4];
            #pragma unroll
            for (int i = 0; i < 4; i++) p[i] = sm.Ss[ty*4 + i][kk];
            float4 vv = *(const float4*)&sm.Vs[kk][tx*4];
            #pragma unroll
            for (int i = 0; i < 4; i++) {
                o[i][0] += p[i] * vv.x; o[i][1] += p[i] * vv.y;
                o[i][2] += p[i] * vv.z; o[i][3] += p[i] * vv.w;
            }
        }
        __syncthreads();
    }

    #pragma unroll
    for (int i = 0; i < 4; i++) {
        int r = ty*4 + i;
        float invl = 1.0f / sm.l[r];
        float4 ov;
        ov.x = o[i][0]*invl; ov.y = o[i][1]*invl;
        ov.z = o[i][2]*invl; ov.w = o[i][3]*invl;
        *(float4*)(ctx + ((size_t)(b * S_ + q0 + r) * D_ + h * HD_ + tx*4)) = ov;
    }
}

// ================= bf16-split tensor-core GEMM ==========================
// C[M,N] = A[M,K] @ B[K,N] (+Res), A fp32 (split in-kernel), B pre-split bf16.
// 3 MMAs per tile: Ah*Bh + Ah*Bl + Al*Bh  (fp32 accum; error ~1e-5).
#define BM_  128
#define BN_  128
#define BKK_ 32
#define AST_ 40     // A smem row stride in bf16 elems (padded, conflict-free)
#define BST_ 136    // B smem row stride in bf16 elems

#define LDSM4(r, addr) \
    asm volatile("ldmatrix.sync.aligned.m8n8.x4.shared.b16 {%0,%1,%2,%3}, [%4];" \
        : "=r"((r)[0]), "=r"((r)[1]), "=r"((r)[2]), "=r"((r)[3]) : "r"(addr))
#define LDSM4T(r, addr) \
    asm volatile("ldmatrix.sync.aligned.m8n8.x4.trans.shared.b16 {%0,%1,%2,%3}, [%4];" \
        : "=r"((r)[0]), "=r"((r)[1]), "=r"((r)[2]), "=r"((r)[3]) : "r"(addr))
#define MMA_BF16(acc, a, b0, b1) \
    asm volatile("mma.sync.aligned.m16n8k16.row.col.f32.bf16.bf16.f32 " \
        "{%0,%1,%2,%3}, {%4,%5,%6,%7}, {%8,%9}, {%0,%1,%2,%3};" \
        : "+f"((acc)[0]), "+f"((acc)[1]), "+f"((acc)[2]), "+f"((acc)[3]) \
        : "r"((a)[0]), "r"((a)[1]), "r"((a)[2]), "r"((a)[3]), "r"(b0), "r"(b1))

__device__ __forceinline__ void stage_A(float4 v, bf16* Ah, bf16* Al, int r, int c4) {
    float vv[4] = {v.x, v.y, v.z, v.w};
    bf16 h[4], l[4];
    #pragma unroll
    for (int j = 0; j < 4; j++) {
        h[j] = __float2bfloat16(vv[j]);
        l[j] = __float2bfloat16(vv[j] - __bfloat162float(h[j]));
    }
    *(uint2*)&Ah[r*AST_ + c4] = make_uint2(pack2(h[0],h[1]), pack2(h[2],h[3]));
    *(uint2*)&Al[r*AST_ + c4] = make_uint2(pack2(l[0],l[1]), pack2(l[2],l[3]));
}

__global__ void __launch_bounds__(256)
bgemm_kernel(const float* __restrict__ A,
             const bf16* __restrict__ Bh, const bf16* __restrict__ Bl,
             const float* __restrict__ Res, float* __restrict__ C,
             int M, int N, int K) {
    __shared__ bf16 Ah[BM_*AST_], Al[BM_*AST_];
    __shared__ bf16 Bhs[BKK_*BST_], Bls[BKK_*BST_];

    const int tid   = threadIdx.x;
    const int lane  = tid & 31, warp = tid >> 5;
    const int warpM = warp >> 1, warpN = warp & 1;   // 4 x 2 warp grid
    const int bx = blockIdx.x, by = blockIdx.y;

    const float* Ag  = A  + (size_t)by * BM_ * K;
    const bf16*  Bhg = Bh + (size_t)bx * BN_;
    const bf16*  Blg = Bl + (size_t)bx * BN_;

    float acc[2][8][4];
    #pragma unroll
    for (int i = 0; i < 2; i++)
        #pragma unroll
        for (int j = 0; j < 8; j++)
            #pragma unroll
            for (int q = 0; q < 4; q++) acc[i][j][q] = 0.f;

    // initial tile load
    #pragma unroll
    for (int p = 0; p < 4; p++) {
        int li = p*256 + tid, r = li >> 3, c4 = (li & 7) * 4;
        stage_A(*(const float4*)(Ag + (size_t)r*K + c4), Ah, Al, r, c4);
    }
    #pragma unroll
    for (int p = 0; p < 2; p++) {
        int li = p*256 + tid, r = li >> 4, c8 = (li & 15) * 8;
        *(uint4*)&Bhs[r*BST_ + c8] = *(const uint4*)(Bhg + (size_t)r*N + c8);
        *(uint4*)&Bls[r*BST_ + c8] = *(const uint4*)(Blg + (size_t)r*N + c8);
    }
    __syncthreads();

    const uint32_t aAddrH = (uint32_t)__cvta_generic_to_shared(Ah);
    const uint32_t aAddrL = (uint32_t)__cvta_generic_to_shared(Al);
    const uint32_t bAddrH = (uint32_t)__cvta_generic_to_shared(Bhs);
    const uint32_t bAddrL = (uint32_t)__cvta_generic_to_shared(Bls);
    const int arow = warpM*32 + (lane & 15);
    const int acol = (lane >> 4) * 8;
    const int brow = (lane & 15);
    const int bcol = warpN*64 + (lane >> 4) * 8;

    const int kIters = K / BKK_;
    for (int it = 0; it < kIters; ++it) {
        // register prefetch of next tile
        float4 pa[4]; uint4 pbh[2], pbl[2];
        const bool nxt = (it + 1) < kIters;
        if (nxt) {
            int k0 = (it + 1) * BKK_;
            #pragma unroll
            for (int p = 0; p < 4; p++) {
                int li = p*256 + tid, r = li >> 3, c4 = (li & 7) * 4;
                pa[p] = *(const float4*)(Ag + (size_t)r*K + k0 + c4);
            }
            #pragma unroll
            for (int p = 0; p < 2; p++) {
                int li = p*256 + tid, r = li >> 4, c8 = (li & 15) * 8;
                pbh[p] = *(const uint4*)(Bhg + (size_t)(k0 + r)*N + c8);
                pbl[p] = *(const uint4*)(Blg + (size_t)(k0 + r)*N + c8);
            }
        }
        // compute current tile
        #pragma unroll
        for (int kk = 0; kk < BKK_; kk += 16) {
            uint32_t ah[2][4], al[2][4];
            #pragma unroll
            for (int mt = 0; mt < 2; mt++) {
                uint32_t off = (uint32_t)(((arow + mt*16)*AST_ + kk + acol) * 2);
                LDSM4(ah[mt], aAddrH + off);
                LDSM4(al[mt], aAddrL + off);
            }
            #pragma unroll
            for (int pr = 0; pr < 4; pr++) {
                uint32_t off = (uint32_t)(((brow + kk)*BST_ + bcol + pr*16) * 2);
                uint32_t bh[4], bl[4];
                LDSM4T(bh, bAddrH + off);
                LDSM4T(bl, bAddrL + off);
                #pragma unroll
                for (int mt = 0; mt < 2; mt++) {
                    #pragma unroll
                    for (int h2 = 0; h2 < 2; h2++) {
                        int nt = pr*2 + h2;
                        MMA_BF16(acc[mt][nt], ah[mt], bh[h2*2], bh[h2*2+1]);
                        MMA_BF16(acc[mt][nt], ah[mt], bl[h2*2], bl[h2*2+1]);
                        MMA_BF16(acc[mt][nt], al[mt], bh[h2*2], bh[h2*2+1]);
                    }
                }
            }
        }
        __syncthreads();
        if (nxt) {
            #pragma unroll
            for (int p = 0; p < 4; p++) {
                int li = p*256 + tid, r = li >> 3, c4 = (li & 7) * 4;
                stage_A(pa[p], Ah, Al, r, c4);
            }
            #pragma unroll
            for (int p = 0; p < 2; p++) {
                int li = p*256 + tid, r = li >> 4, c8 = (li & 15) * 8;
                *(uint4*)&Bhs[r*BST_ + c8] = pbh[p];
                *(uint4*)&Bls[r*BST_ + c8] = pbl[p];
            }
        }
        __syncthreads();
    }

    // epilogue
    const int g = lane >> 2, tg = lane & 3;
    #pragma unroll
    for (int mt = 0; mt < 2; mt++) {
        #pragma unroll
        for (int nt = 0; nt < 8; nt++) {
            size_t r0 = (size_t)by*BM_ + warpM*32 + mt*16 + g;
            size_t c  = (size_t)bx*BN_ + warpN*64 + nt*8 + tg*2;
            float2 v0 = make_float2(acc[mt][nt][0], acc[mt][nt][1]);
            float2 v1 = make_float2(acc[mt][nt][2], acc[mt][nt][3]);
            if (Res) {
                float2 q0 = *(const float2*)(Res + r0*N + c);
                float2 q1 = *(const float2*)(Res + (r0+8)*N + c);
                v0.x += q0.x; v0.y += q0.y; v1.x += q1.x; v1.y += q1.y;
            }
            *(float2*)(C + r0*N + c)     = v0;
            *(float2*)(C + (r0+8)*N + c) = v1;
        }
    }
}

// ---------------- SwiGLU elementwise ----------------
__global__ void silu_mult_kernel(float* __restrict__ g, const float* __restrict__ u) {
    int i = blockIdx.x * blockDim.x + threadIdx.x;
    float4 gv = ((const float4*)g)[i];
    float4 uv = ((const float4*)u)[i];
    gv.x = gv.x / (1.f + expf(-gv.x)) * uv.x;
    gv.y = gv.y / (1.f + expf(-gv.y)) * uv.y;
    gv.z = gv.z / (1.f + expf(-gv.z)) * uv.z;
    gv.w = gv.w / (1.f + expf(-gv.w)) * uv.w;
    ((float4*)g)[i] = gv;
}

// ---------------- host orchestration ----------------
static inline void run_bgemm(const float* A, const bf16* Bh, const bf16* Bl,
                             const float* Res, float* C, int M, int N, int K) {
    dim3 grid(N / BN_, M / BM_);
    bgemm_kernel<<<grid, 256>>>(A, Bh, Bl, Res, C, M, N, K);
}

static inline void run_split(const float* src, bf16* h, bf16* l, size_t n) {
    int n4 = (int)(n / 4);
    split_kernel<<<(n4 + 255) / 256, 256>>>(src, h, l, n4);
}

extern "C" void kernel_launch(void* const* d_in, const int* in_sizes, int n_in,
                              void* d_out, int out_size) {
    const void*  idx    = d_in[0];
    const float* emb    = (const float*)d_in[1];
    const float* wq     = (const float*)d_in[2];
    const float* wk     = (const float*)d_in[3];
    const float* wv     = (const float*)d_in[4];
    const float* wo     = (const float*)d_in[5];
    const float* wgate  = (const float*)d_in[6];
    const float* wup    = (const float*)d_in[7];
    const float* wdown  = (const float*)d_in[8];
    const float* na     = (const float*)d_in[9];
    const float* nf     = (const float*)d_in[10];
    const float* nfin   = (const float*)d_in[11];
    const float* wout   = (const float*)d_in[12];

    float *x, *n, *q, *k, *v, *ctx, *gate, *up;
    cudaGetSymbolAddress((void**)&x,    g_x);
    cudaGetSymbolAddress((void**)&n,    g_n);
    cudaGetSymbolAddress((void**)&q,    g_q);
    cudaGetSymbolAddress((void**)&k,    g_k);
    cudaGetSymbolAddress((void**)&v,    g_v);
    cudaGetSymbolAddress((void**)&ctx,  g_ctx);
    cudaGetSymbolAddress((void**)&gate, g_gate);
    cudaGetSymbolAddress((void**)&up,   g_up);

    bf16 *wq_h,*wq_l,*wk_h,*wk_l,*wv_h,*wv_l,*wo_h,*wo_l;
    bf16 *wg_h,*wg_l,*wu_h,*wu_l,*wd_h,*wd_l,*wout_h,*wout_l;
    cudaGetSymbolAddress((void**)&wq_h, g_wq_h);  cudaGetSymbolAddress((void**)&wq_l, g_wq_l);
    cudaGetSymbolAddress((void**)&wk_h, g_wk_h);  cudaGetSymbolAddress((void**)&wk_l, g_wk_l);
    cudaGetSymbolAddress((void**)&wv_h, g_wv_h);  cudaGetSymbolAddress((void**)&wv_l, g_wv_l);
    cudaGetSymbolAddress((void**)&wo_h, g_wo_h);  cudaGetSymbolAddress((void**)&wo_l, g_wo_l);
    cudaGetSymbolAddress((void**)&wg_h, g_wg_h);  cudaGetSymbolAddress((void**)&wg_l, g_wg_l);
    cudaGetSymbolAddress((void**)&wu_h, g_wu_h);  cudaGetSymbolAddress((void**)&wu_l, g_wu_l);
    cudaGetSymbolAddress((void**)&wd_h, g_wd_h);  cudaGetSymbolAddress((void**)&wd_l, g_wd_l);
    cudaGetSymbolAddress((void**)&wout_h, g_wout_h); cudaGetSymbolAddress((void**)&wout_l, g_wout_l);

    static const int FLASH_SMEM = sizeof(FlashSmem);
    cudaFuncSetAttribute(flash_kernel,
                         cudaFuncAttributeMaxDynamicSharedMemorySize, FLASH_SMEM);

    // split all weights to bf16 hi/lo planes
    run_split(wq,    wq_h,   wq_l,   (size_t)L_*D_*D_);
    run_split(wk,    wk_h,   wk_l,   (size_t)L_*D_*KVH_*HD_);
    run_split(wv,    wv_h,   wv_l,   (size_t)L_*D_*KVH_*HD_);
    run_split(wo,    wo_h,   wo_l,   (size_t)L_*D_*D_);
    run_split(wgate, wg_h,   wg_l,   (size_t)L_*D_*F_);
    run_split(wup,   wu_h,   wu_l,   (size_t)L_*D_*F_);
    run_split(wdown, wd_h,   wd_l,   (size_t)L_*F_*D_);
    run_split(wout,  wout_h, wout_l, (size_t)D_*V_);

    detect_idx_kernel<<<1, 256>>>((const int*)idx);
    embed_kernel<<<T_, 256>>>(idx, emb);

    for (int l = 0; l < L_; l++) {
        size_t oD  = (size_t)l * D_ * D_;
        size_t oKV = (size_t)l * D_ * KVH_ * HD_;
        size_t oF  = (size_t)l * D_ * F_;
        rmsnorm_kernel<<<T_, 256>>>(x, na + (size_t)l * D_, n);
        run_bgemm(n, wq_h + oD,  wq_l + oD,  nullptr, q, T_, D_,       D_);
        run_bgemm(n, wk_h + oKV, wk_l + oKV, nullptr, k, T_, KVH_*HD_, D_);
        run_bgemm(n, wv_h + oKV, wv_l + oKV, nullptr, v, T_, KVH_*HD_, D_);
        rope_kernel<<<T_, H_ * 32>>>(q, H_);
        rope_kernel<<<T_, KVH_ * 32>>>(k, KVH_);
        flash_kernel<<<dim3(S_ / BQ, H_, B_), 256, FLASH_SMEM>>>(q, k, v, ctx);
        run_bgemm(ctx, wo_h + oD, wo_l + oD, x, x, T_, D_, D_);         // x += ctx@wo
        rmsnorm_kernel<<<T_, 256>>>(x, nf + (size_t)l * D_, n);
        run_bgemm(n, wg_h + oF, wg_l + oF, nullptr, gate, T_, F_, D_);
        run_bgemm(n, wu_h + oF, wu_l + oF, nullptr, up,   T_, F_, D_);
        silu_mult_kernel<<<(T_ * F_ / 4) / 256, 256>>>(gate, up);
        run_bgemm(gate, wd_h + (size_t)l*F_*D_, wd_l + (size_t)l*F_*D_,
                  x, x, T_, D_, F_);                                    // x += h@wdown
    }

    rmsnorm_kernel<<<T_, 256>>>(x, nfin, n);
    run_bgemm(n, wout_h, wout_l, nullptr, (float*)d_out, T_, V_, D_);
}

// round 3
// speedup vs baseline: 3.1511x; 1.5367x over previous
#include <cuda_runtime.h>
#include <cuda_bf16.h>
#include <math.h>
#include <stdint.h>

// ---------------- problem constants ----------------
#define V_   32000
#define D_   1024
#define H_   16
#define KVH_ 4
#define HD_  64
#define F_   4096
#define L_   2
#define B_   2
#define S_   2048
#define T_   (B_*S_)
#define REP_ (H_/KVH_)
#define EPS_ 1e-5f
#define SCALE_ 0.125f

typedef __nv_bfloat16 bf16;

// ---------------- scratch ----------------
__device__ float g_x  [T_*D_];
__device__ float g_q  [T_*D_];
__device__ float g_k  [T_*KVH_*HD_];
__device__ float g_v  [T_*KVH_*HD_];
__device__ float g_gate[T_*F_];
__device__ float g_up  [T_*F_];
__device__ int   g_is64;

// activation bf16 hi/lo planes
__device__ bf16 g_nh[T_*D_],  g_nl[T_*D_];
__device__ bf16 g_qh[T_*D_],  g_ql[T_*D_];
__device__ bf16 g_kh[T_*KVH_*HD_], g_kl[T_*KVH_*HD_];
__device__ bf16 g_vh[T_*KVH_*HD_], g_vl[T_*KVH_*HD_];
__device__ bf16 g_ch[T_*D_],  g_cl[T_*D_];
__device__ bf16 g_gh[T_*F_],  g_gl[T_*F_];

// weight bf16 hi/lo planes
__device__ bf16 g_wq_h [L_*D_*D_],        g_wq_l [L_*D_*D_];
__device__ bf16 g_wk_h [L_*D_*KVH_*HD_],  g_wk_l [L_*D_*KVH_*HD_];
__device__ bf16 g_wv_h [L_*D_*KVH_*HD_],  g_wv_l [L_*D_*KVH_*HD_];
__device__ bf16 g_wo_h [L_*D_*D_],        g_wo_l [L_*D_*D_];
__device__ bf16 g_wg_h [L_*D_*F_],        g_wg_l [L_*D_*F_];
__device__ bf16 g_wu_h [L_*D_*F_],        g_wu_l [L_*D_*F_];
__device__ bf16 g_wd_h [L_*F_*D_],        g_wd_l [L_*F_*D_];
__device__ bf16 g_wout_h[D_*V_],          g_wout_l[D_*V_];

// ---------------- helpers ----------------
__device__ __forceinline__ uint32_t pack2(bf16 a, bf16 b) {
    __nv_bfloat162 t = __halves2bfloat162(a, b);
    return *reinterpret_cast<uint32_t*>(&t);
}
__device__ __forceinline__ void split1(float v, bf16& h, bf16& l) {
    h = __float2bfloat16(v);
    l = __float2bfloat16(v - __bfloat162float(h));
}

#define LDSM4(r, addr) \
    asm volatile("ldmatrix.sync.aligned.m8n8.x4.shared.b16 {%0,%1,%2,%3}, [%4];" \
        : "=r"((r)[0]), "=r"((r)[1]), "=r"((r)[2]), "=r"((r)[3]) : "r"(addr))
#define LDSM4T(r, addr) \
    asm volatile("ldmatrix.sync.aligned.m8n8.x4.trans.shared.b16 {%0,%1,%2,%3}, [%4];" \
        : "=r"((r)[0]), "=r"((r)[1]), "=r"((r)[2]), "=r"((r)[3]) : "r"(addr))
#define MMA_BF16(acc, a, b0, b1) \
    asm volatile("mma.sync.aligned.m16n8k16.row.col.f32.bf16.bf16.f32 " \
        "{%0,%1,%2,%3}, {%4,%5,%6,%7}, {%8,%9}, {%0,%1,%2,%3};" \
        : "+f"((acc)[0]), "+f"((acc)[1]), "+f"((acc)[2]), "+f"((acc)[3]) \
        : "r"((a)[0]), "r"((a)[1]), "r"((a)[2]), "r"((a)[3]), "r"(b0), "r"(b1))
#define CP16(dst, src) \
    asm volatile("cp.async.cg.shared.global [%0], [%1], 16;\n" :: "r"(dst), "l"(src) : "memory")
#define CP_COMMIT() asm volatile("cp.async.commit_group;\n" ::: "memory")
#define CP_WAIT(n)  asm volatile("cp.async.wait_group %0;\n" :: "n"(n) : "memory")

// ---------------- weight/act fp32 -> bf16 hi/lo split ----------------
__global__ void split_kernel(const float* __restrict__ in,
                             bf16* __restrict__ hi, bf16* __restrict__ lo, int n4) {
    int i = blockIdx.x * blockDim.x + threadIdx.x;
    if (i >= n4) return;
    float4 v = ((const float4*)in)[i];
    float vv[4] = {v.x, v.y, v.z, v.w};
    bf16 h[4], l[4];
    #pragma unroll
    for (int j = 0; j < 4; j++) split1(vv[j], h[j], l[j]);
    ((uint2*)hi)[i] = make_uint2(pack2(h[0],h[1]), pack2(h[2],h[3]));
    ((uint2*)lo)[i] = make_uint2(pack2(l[0],l[1]), pack2(l[2],l[3]));
}

// ---------------- idx detection + embed ----------------
__global__ void detect_idx_kernel(const int* idx) {
    __shared__ int ok;
    if (threadIdx.x == 0) ok = 1;
    __syncthreads();
    int bad = 0;
    for (int i = threadIdx.x; i < T_/2; i += blockDim.x)
        if (idx[2*i + 1] != 0) bad = 1;
    if (bad) atomicAnd(&ok, 0);
    __syncthreads();
    if (threadIdx.x == 0) g_is64 = ok;
}
__global__ void embed_kernel(const void* idx, const float* __restrict__ emb) {
    int t = blockIdx.x;
    int tok = g_is64 ? (int)((const long long*)idx)[t] : ((const int*)idx)[t];
    ((float4*)(g_x + (size_t)t * D_))[threadIdx.x] =
        ((const float4*)(emb + (size_t)tok * D_))[threadIdx.x];
}

// ---------------- RMSNorm -> bf16 planes ----------------
__global__ void rmsnorm_split_kernel(const float* __restrict__ x,
                                     const float* __restrict__ w,
                                     bf16* __restrict__ oh, bf16* __restrict__ ol) {
    int t = blockIdx.x;
    __shared__ float red[8];
    float4 v = ((const float4*)(x + (size_t)t * D_))[threadIdx.x];
    float ss = v.x*v.x + v.y*v.y + v.z*v.z + v.w*v.w;
    #pragma unroll
    for (int o = 16; o > 0; o >>= 1) ss += __shfl_xor_sync(0xffffffffu, ss, o);
    if ((threadIdx.x & 31) == 0) red[threadIdx.x >> 5] = ss;
    __syncthreads();
    if (threadIdx.x < 8) {
        float s = red[threadIdx.x];
        #pragma unroll
        for (int o = 4; o > 0; o >>= 1) s += __shfl_xor_sync(0xffu, s, o);
        if (threadIdx.x == 0) red[0] = s;
    }
    __syncthreads();
    float inv = rsqrtf(red[0] * (1.0f / D_) + EPS_);
    float4 wv = ((const float4*)w)[threadIdx.x];
    float vv[4] = {v.x*inv*wv.x, v.y*inv*wv.y, v.z*inv*wv.z, v.w*inv*wv.w};
    bf16 h[4], l[4];
    #pragma unroll
    for (int j = 0; j < 4; j++) split1(vv[j], h[j], l[j]);
    ((uint2*)(oh + (size_t)t*D_))[threadIdx.x] = make_uint2(pack2(h[0],h[1]), pack2(h[2],h[3]));
    ((uint2*)(ol + (size_t)t*D_))[threadIdx.x] = make_uint2(pack2(l[0],l[1]), pack2(l[2],l[3]));
}

// ---------------- RoPE -> bf16 planes (optionally scaled) ----------------
__global__ void rope_split_kernel(const float* __restrict__ x,
                                  bf16* __restrict__ xh, bf16* __restrict__ xl,
                                  int nheads, float scl) {
    int t   = blockIdx.x;
    int pos = t % S_;
    int j   = threadIdx.x & 31;
    int h   = threadIdx.x >> 5;
    float invf = powf(500000.0f, -(float)(2 * j) / (float)HD_);
    float ang = (float)pos * invf;
    float s, c;
    sincosf(ang, &s, &c);
    size_t base = (size_t)t * nheads * HD_ + h * HD_;
    const float* p = x + base;
    float a = p[j], b = p[j + 32];
    float r0 = (a * c - b * s) * scl;
    float r1 = (b * c + a * s) * scl;
    bf16 h0, l0, h1, l1;
    split1(r0, h0, l0); split1(r1, h1, l1);
    xh[base + j] = h0; xl[base + j] = l0;
    xh[base + j + 32] = h1; xl[base + j + 32] = l1;
}

// ---------------- SwiGLU -> bf16 planes ----------------
__global__ void silu_split_kernel(const float* __restrict__ g, const float* __restrict__ u,
                                  bf16* __restrict__ oh, bf16* __restrict__ ol) {
    int i = blockIdx.x * blockDim.x + threadIdx.x;
    float4 gv = ((const float4*)g)[i];
    float4 uv = ((const float4*)u)[i];
    float vv[4];
    vv[0] = gv.x / (1.f + __expf(-gv.x)) * uv.x;
    vv[1] = gv.y / (1.f + __expf(-gv.y)) * uv.y;
    vv[2] = gv.z / (1.f + __expf(-gv.z)) * uv.z;
    vv[3] = gv.w / (1.f + __expf(-gv.w)) * uv.w;
    bf16 h[4], l[4];
    #pragma unroll
    for (int j = 0; j < 4; j++) split1(vv[j], h[j], l[j]);
    ((uint2*)oh)[i] = make_uint2(pack2(h[0],h[1]), pack2(h[2],h[3]));
    ((uint2*)ol)[i] = make_uint2(pack2(l[0],l[1]), pack2(l[2],l[3]));
}

// ================= bgemm v2: cp.async double-buffered, pre-split A ======
// C[M,N] = (Ah+Al)[M,K] @ (Bh+Bl)[K,N] (+Res); 3 MMAs (hh, hl, lh).
#define BM_  128
#define BN_  128
#define BKK_ 32
#define AST_ 40
#define BST_ 136
#define ASZ_ (BM_*AST_)
#define BSZ_ (BKK_*BST_)

__global__ void __launch_bounds__(256)
bgemm_kernel(const bf16* __restrict__ Ahg, const bf16* __restrict__ Alg,
             const bf16* __restrict__ Bhg, const bf16* __restrict__ Blg,
             const float* __restrict__ Res, float* __restrict__ C,
             int M, int N, int K) {
    extern __shared__ bf16 sm[];
    bf16* sAh = sm;                 // 2 stages
    bf16* sAl = sAh + 2*ASZ_;
    bf16* sBh = sAl + 2*ASZ_;
    bf16* sBl = sBh + 2*BSZ_;

    const int tid  = threadIdx.x;
    const int lane = tid & 31, warp = tid >> 5;
    const int warpM = warp >> 1, warpN = warp & 1;
    const int bx = blockIdx.x, by = blockIdx.y;

    const bf16* Ahb = Ahg + (size_t)by * BM_ * K;
    const bf16* Alb = Alg + (size_t)by * BM_ * K;
    const bf16* Bhb = Bhg + (size_t)bx * BN_;
    const bf16* Blb = Blg + (size_t)bx * BN_;

    const uint32_t uAh = (uint32_t)__cvta_generic_to_shared(sAh);
    const uint32_t uAl = (uint32_t)__cvta_generic_to_shared(sAl);
    const uint32_t uBh = (uint32_t)__cvta_generic_to_shared(sBh);
    const uint32_t uBl = (uint32_t)__cvta_generic_to_shared(sBl);

    // load-index precompute
    const int ar = tid >> 2, ac = (tid & 3) * 8;        // A: 128 rows x 4 chunks
    const int br = tid >> 4, bc = (tid & 15) * 8;       // B: 16 rows x 16 chunks (x2)

    auto load_tile = [&](int st, int k0) {
        // A planes: 512 chunks each -> 2 per thread
        #pragma unroll
        for (int p = 0; p < 2; p++) {
            int r = ar + p*64;
            uint32_t d = (uint32_t)((st*ASZ_ + r*AST_ + ac) * 2);
            CP16(uAh + d, Ahb + (size_t)r*K + k0 + ac);
            CP16(uAl + d, Alb + (size_t)r*K + k0 + ac);
        }
        // B planes: 512 chunks each -> 2 per thread
        #pragma unroll
        for (int p = 0; p < 2; p++) {
            int r = br + p*16;
            uint32_t d = (uint32_t)((st*BSZ_ + r*BST_ + bc) * 2);
            CP16(uBh + d, Bhb + (size_t)(k0 + r)*N + bc);
            CP16(uBl + d, Blb + (size_t)(k0 + r)*N + bc);
        }
    };

    float acc[2][8][4];
    #pragma unroll
    for (int i = 0; i < 2; i++)
        #pragma unroll
        for (int j = 0; j < 8; j++)
            #pragma unroll
            for (int q = 0; q < 4; q++) acc[i][j][q] = 0.f;

    const int arow = warpM*32 + (lane & 15);
    const int acol = (lane >> 4) * 8;
    const int brow = (lane & 15);
    const int bcol = warpN*64 + (lane >> 4) * 8;

    const int kIters = K / BKK_;
    load_tile(0, 0);
    CP_COMMIT();

    for (int it = 0; it < kIters; ++it) {
        if (it + 1 < kIters) {
            load_tile((it+1)&1, (it+1)*BKK_);
            CP_COMMIT();
            CP_WAIT(1);
        } else {
            CP_WAIT(0);
        }
        __syncthreads();
        const int st = it & 1;
        const uint32_t aH = uAh + (uint32_t)(st*ASZ_*2);
        const uint32_t aL = uAl + (uint32_t)(st*ASZ_*2);
        const uint32_t bH = uBh + (uint32_t)(st*BSZ_*2);
        const uint32_t bL = uBl + (uint32_t)(st*BSZ_*2);
        #pragma unroll
        for (int kk = 0; kk < BKK_; kk += 16) {
            uint32_t ah[2][4], al[2][4];
            #pragma unroll
            for (int mt = 0; mt < 2; mt++) {
                uint32_t off = (uint32_t)(((arow + mt*16)*AST_ + kk + acol) * 2);
                LDSM4(ah[mt], aH + off);
                LDSM4(al[mt], aL + off);
            }
            #pragma unroll
            for (int pr = 0; pr < 4; pr++) {
                uint32_t off = (uint32_t)(((brow + kk)*BST_ + bcol + pr*16) * 2);
                uint32_t bh[4], bl[4];
                LDSM4T(bh, bH + off);
                LDSM4T(bl, bL + off);
                #pragma unroll
                for (int mt = 0; mt < 2; mt++) {
                    #pragma unroll
                    for (int h2 = 0; h2 < 2; h2++) {
                        int nt = pr*2 + h2;
                        MMA_BF16(acc[mt][nt], ah[mt], bh[h2*2], bh[h2*2+1]);
                        MMA_BF16(acc[mt][nt], ah[mt], bl[h2*2], bl[h2*2+1]);
                        MMA_BF16(acc[mt][nt], al[mt], bh[h2*2], bh[h2*2+1]);
                    }
                }
            }
        }
        __syncthreads();
    }

    const int g = lane >> 2, tg = lane & 3;
    #pragma unroll
    for (int mt = 0; mt < 2; mt++) {
        #pragma unroll
        for (int nt = 0; nt < 8; nt++) {
            size_t r0 = (size_t)by*BM_ + warpM*32 + mt*16 + g;
            size_t c  = (size_t)bx*BN_ + warpN*64 + nt*8 + tg*2;
            float2 v0 = make_float2(acc[mt][nt][0], acc[mt][nt][1]);
            float2 v1 = make_float2(acc[mt][nt][2], acc[mt][nt][3]);
            if (Res) {
                float2 q0 = *(const float2*)(Res + r0*N + c);
                float2 q1 = *(const float2*)(Res + (r0+8)*N + c);
                v0.x += q0.x; v0.y += q0.y; v1.x += q1.x; v1.y += q1.y;
            }
            *(float2*)(C + r0*N + c)     = v0;
            *(float2*)(C + (r0+8)*N + c) = v1;
        }
    }
}

// ================= tensor-core flash attention =========================
// 64 q-rows per block, 128 threads (4 warps x 16 rows), KV tiles of 64.
// Q pre-scaled by SCALE_. All operands bf16 hi/lo split, 3-MMA products.
#define FST 72
#define FQSZ (64*FST)

__global__ void __launch_bounds__(128)
flash_tc_kernel(const bf16* __restrict__ qh, const bf16* __restrict__ ql,
                const bf16* __restrict__ kh, const bf16* __restrict__ kl,
                const bf16* __restrict__ vh, const bf16* __restrict__ vl,
                bf16* __restrict__ ch, bf16* __restrict__ cl) {
    extern __shared__ bf16 fsm[];
    bf16* sQh = fsm;
    bf16* sQl = sQh + FQSZ;
    bf16* sKh = sQl + FQSZ;
    bf16* sKl = sKh + FQSZ;
    bf16* sVh = sKl + FQSZ;
    bf16* sVl = sVh + FQSZ;

    const int q0  = blockIdx.x * 64;
    const int h   = blockIdx.y;
    const int b   = blockIdx.z;
    const int kvh = h / REP_;
    const int tid = threadIdx.x;
    const int lane = tid & 31, warp = tid >> 5;
    const int g = lane >> 2, tg = lane & 3;

    // load Q tile (both planes): 64 rows x 64 bf16 = 8 chunks/row
    for (int li = tid; li < 512; li += 128) {
        int r = li >> 3, c8 = (li & 7) * 8;
        size_t src = ((size_t)(b * S_ + q0 + r) * D_ + h * HD_ + c8);
        *(uint4*)&sQh[r*FST + c8] = *(const uint4*)(qh + src);
        *(uint4*)&sQl[r*FST + c8] = *(const uint4*)(ql + src);
    }

    float mrow[2] = {-INFINITY, -INFINITY};
    float lrow[2] = {0.f, 0.f};
    float o[8][4] = {};

    const uint32_t uQh = (uint32_t)__cvta_generic_to_shared(sQh);
    const uint32_t uQl = (uint32_t)__cvta_generic_to_shared(sQl);
    const uint32_t uKh = (uint32_t)__cvta_generic_to_shared(sKh);
    const uint32_t uKl = (uint32_t)__cvta_generic_to_shared(sKl);
    const uint32_t uVh = (uint32_t)__cvta_generic_to_shared(sVh);
    const uint32_t uVl = (uint32_t)__cvta_generic_to_shared(sVl);
    const int fr = (lane & 15);
    const int fc = (lane >> 4) * 8;

    const int ntiles = q0 / 64 + 1;
    for (int tI = 0; tI < ntiles; tI++) {
        int kv0 = tI * 64;
        __syncthreads();   // protect smem reuse from previous iteration
        for (int li = tid; li < 512; li += 128) {
            int r = li >> 3, c8 = (li & 7) * 8;
            size_t src = ((size_t)(b * S_ + kv0 + r) * (KVH_*HD_) + kvh * HD_ + c8);
            *(uint4*)&sKh[r*FST + c8] = *(const uint4*)(kh + src);
            *(uint4*)&sKl[r*FST + c8] = *(const uint4*)(kl + src);
            *(uint4*)&sVh[r*FST + c8] = *(const uint4*)(vh + src);
            *(uint4*)&sVl[r*FST + c8] = *(const uint4*)(vl + src);
        }
        __syncthreads();

        // ---- S = (Q*scale) K^T  (bf16-split, 3 MMA) ----
        float s[8][4] = {};
        #pragma unroll
        for (int kk = 0; kk < 64; kk += 16) {
            uint32_t aqh[4], aql[4];
            uint32_t qoff = (uint32_t)(((warp*16 + fr)*FST + kk + fc) * 2);
            LDSM4(aqh, uQh + qoff);
            LDSM4(aql, uQl + qoff);
            #pragma unroll
            for (int nb = 0; nb < 4; nb++) {
                uint32_t koff = (uint32_t)(((nb*16 + fr)*FST + kk + fc) * 2);
                uint32_t k4h[4], k4l[4];
                LDSM4(k4h, uKh + koff);
                LDSM4(k4l, uKl + koff);
                MMA_BF16(s[nb*2],   aqh, k4h[0], k4h[2]);
                MMA_BF16(s[nb*2],   aqh, k4l[0], k4l[2]);
                MMA_BF16(s[nb*2],   aql, k4h[0], k4h[2]);
                MMA_BF16(s[nb*2+1], aqh, k4h[1], k4h[3]);
                MMA_BF16(s[nb*2+1], aqh, k4l[1], k4l[3]);
                MMA_BF16(s[nb*2+1], aql, k4h[1], k4h[3]);
            }
        }

        // ---- causal mask on diagonal tile ----
        if (tI == ntiles - 1) {
            #pragma unroll
            for (int nt = 0; nt < 8; nt++) {
                int col = kv0 + nt*8 + tg*2;
                int r0g = q0 + warp*16 + g;
                if (col     > r0g)   s[nt][0] = -INFINITY;
                if (col + 1 > r0g)   s[nt][1] = -INFINITY;
                if (col     > r0g+8) s[nt][2] = -INFINITY;
                if (col + 1 > r0g+8) s[nt][3] = -INFINITY;
            }
        }

        // ---- streaming softmax (registers + quad shuffles) ----
        #pragma unroll
        for (int qi = 0; qi < 2; qi++) {
            float mx = -INFINITY;
            #pragma unroll
            for (int nt = 0; nt < 8; nt++)
                mx = fmaxf(mx, fmaxf(s[nt][qi*2], s[nt][qi*2+1]));
            mx = fmaxf(mx, __shfl_xor_sync(0xffffffffu, mx, 1));
            mx = fmaxf(mx, __shfl_xor_sync(0xffffffffu, mx, 2));
            float mnew = fmaxf(mrow[qi], mx);
            float scale = __expf(mrow[qi] - mnew);
            mrow[qi] = mnew;
            float sum = 0.f;
            #pragma unroll
            for (int nt = 0; nt < 8; nt++) {
                float p0 = __expf(s[nt][qi*2]   - mnew);
                float p1 = __expf(s[nt][qi*2+1] - mnew);
                s[nt][qi*2] = p0; s[nt][qi*2+1] = p1;
                sum += p0 + p1;
            }
            sum += __shfl_xor_sync(0xffffffffu, sum, 1);
            sum += __shfl_xor_sync(0xffffffffu, sum, 2);
            lrow[qi] = lrow[qi]*scale + sum;
            #pragma unroll
            for (int nt = 0; nt < 8; nt++) {
                o[nt][qi*2]   *= scale;
                o[nt][qi*2+1] *= scale;
            }
        }

        // ---- O += P V  (P built in registers from S fragments) ----
        #pragma unroll
        for (int ks = 0; ks < 4; ks++) {
            const float* s0 = s[2*ks];
            const float* s1 = s[2*ks+1];
            uint32_t ph[4], pl[4];
            {
                bf16 h0,l0,h1,l1;
                split1(s0[0], h0, l0); split1(s0[1], h1, l1);
                ph[0] = pack2(h0,h1); pl[0] = pack2(l0,l1);
                split1(s0[2], h0, l0); split1(s0[3], h1, l1);
                ph[1] = pack2(h0,h1); pl[1] = pack2(l0,l1);
                split1(s1[0], h0, l0); split1(s1[1], h1, l1);
                ph[2] = pack2(h0,h1); pl[2] = pack2(l0,l1);
                split1(s1[2], h0, l0); split1(s1[3], h1, l1);
                ph[3] = pack2(h0,h1); pl[3] = pack2(l0,l1);
            }
            #pragma unroll
            for (int nb = 0; nb < 4; nb++) {
                uint32_t voff = (uint32_t)(((ks*16 + fr)*FST + nb*16 + fc) * 2);
                uint32_t v4h[4], v4l[4];
                LDSM4T(v4h, uVh + voff);
                LDSM4T(v4l, uVl + voff);
                MMA_BF16(o[nb*2],   ph, v4h[0], v4h[1]);
                MMA_BF16(o[nb*2],   ph, v4l[0], v4l[1]);
                MMA_BF16(o[nb*2],   pl, v4h[0], v4h[1]);
                MMA_BF16(o[nb*2+1], ph, v4h[2], v4h[3]);
                MMA_BF16(o[nb*2+1], ph, v4l[2], v4l[3]);
                MMA_BF16(o[nb*2+1], pl, v4h[2], v4h[3]);
            }
        }
    }

    // ---- normalize + write ctx planes ----
    #pragma unroll
    for (int qi = 0; qi < 2; qi++) {
        float inv = 1.0f / lrow[qi];
        int r = q0 + warp*16 + g + qi*8;
        size_t base = (size_t)(b * S_ + r) * D_ + h * HD_;
        #pragma unroll
        for (int nt = 0; nt < 8; nt++) {
            int c = nt*8 + tg*2;
            float v0 = o[nt][qi*2]   * inv;
            float v1 = o[nt][qi*2+1] * inv;
            bf16 h0,l0,h1,l1;
            split1(v0, h0, l0); split1(v1, h1, l1);
            *(uint32_t*)(ch + base + c) = pack2(h0,h1);
            *(uint32_t*)(cl + base + c) = pack2(l0,l1);
        }
    }
}

// ---------------- host orchestration ----------------
#define BG_SMEM ((2*ASZ_*2 + 2*BSZ_*2) * 2)   // bytes: (A:2 planes + B:2 planes) x2 stages
#define FL_SMEM (6 * FQSZ * 2)

static inline void run_bgemm(const bf16* Ah, const bf16* Al,
                             const bf16* Bh, const bf16* Bl,
                             const float* Res, float* C, int M, int N, int K) {
    dim3 grid(N / BN_, M / BM_);
    bgemm_kernel<<<grid, 256, BG_SMEM>>>(Ah, Al, Bh, Bl, Res, C, M, N, K);
}
static inline void run_split(const float* src, bf16* h, bf16* l, size_t n) {
    int n4 = (int)(n / 4);
    split_kernel<<<(n4 + 255) / 256, 256>>>(src, h, l, n4);
}

extern "C" void kernel_launch(void* const* d_in, const int* in_sizes, int n_in,
                              void* d_out, int out_size) {
    const void*  idx    = d_in[0];
    const float* emb    = (const float*)d_in[1];
    const float* wq     = (const float*)d_in[2];
    const float* wk     = (const float*)d_in[3];
    const float* wv     = (const float*)d_in[4];
    const float* wo     = (const float*)d_in[5];
    const float* wgate  = (const float*)d_in[6];
    const float* wup    = (const float*)d_in[7];
    const float* wdown  = (const float*)d_in[8];
    const float* na     = (const float*)d_in[9];
    const float* nf     = (const float*)d_in[10];
    const float* nfin   = (const float*)d_in[11];
    const float* wout   = (const float*)d_in[12];

    float *x, *q, *k, *v, *gate, *up;
    cudaGetSymbolAddress((void**)&x,    g_x);
    cudaGetSymbolAddress((void**)&q,    g_q);
    cudaGetSymbolAddress((void**)&k,    g_k);
    cudaGetSymbolAddress((void**)&v,    g_v);
    cudaGetSymbolAddress((void**)&gate, g_gate);
    cudaGetSymbolAddress((void**)&up,   g_up);

    bf16 *nh,*nl,*qh,*ql,*kh,*kl,*vh,*vl,*ch,*cl,*gh,*gl;
    cudaGetSymbolAddress((void**)&nh, g_nh); cudaGetSymbolAddress((void**)&nl, g_nl);
    cudaGetSymbolAddress((void**)&qh, g_qh); cudaGetSymbolAddress((void**)&ql, g_ql);
    cudaGetSymbolAddress((void**)&kh, g_kh); cudaGetSymbolAddress((void**)&kl, g_kl);
    cudaGetSymbolAddress((void**)&vh, g_vh); cudaGetSymbolAddress((void**)&vl, g_vl);
    cudaGetSymbolAddress((void**)&ch, g_ch); cudaGetSymbolAddress((void**)&cl, g_cl);
    cudaGetSymbolAddress((void**)&gh, g_gh); cudaGetSymbolAddress((void**)&gl, g_gl);

    bf16 *wq_h,*wq_l,*wk_h,*wk_l,*wv_h,*wv_l,*wo_h,*wo_l;
    bf16 *wg_h,*wg_l,*wu_h,*wu_l,*wd_h,*wd_l,*wout_h,*wout_l;
    cudaGetSymbolAddress((void**)&wq_h, g_wq_h);  cudaGetSymbolAddress((void**)&wq_l, g_wq_l);
    cudaGetSymbolAddress((void**)&wk_h, g_wk_h);  cudaGetSymbolAddress((void**)&wk_l, g_wk_l);
    cudaGetSymbolAddress((void**)&wv_h, g_wv_h);  cudaGetSymbolAddress((void**)&wv_l, g_wv_l);
    cudaGetSymbolAddress((void**)&wo_h, g_wo_h);  cudaGetSymbolAddress((void**)&wo_l, g_wo_l);
    cudaGetSymbolAddress((void**)&wg_h, g_wg_h);  cudaGetSymbolAddress((void**)&wg_l, g_wg_l);
    cudaGetSymbolAddress((void**)&wu_h, g_wu_h);  cudaGetSymbolAddress((void**)&wu_l, g_wu_l);
    cudaGetSymbolAddress((void**)&wd_h, g_wd_h);  cudaGetSymbolAddress((void**)&wd_l, g_wd_l);
    cudaGetSymbolAddress((void**)&wout_h, g_wout_h); cudaGetSymbolAddress((void**)&wout_l, g_wout_l);

    cudaFuncSetAttribute(bgemm_kernel,
                         cudaFuncAttributeMaxDynamicSharedMemorySize, BG_SMEM);
    cudaFuncSetAttribute(flash_tc_kernel,
                         cudaFuncAttributeMaxDynamicSharedMemorySize, FL_SMEM);

    run_split(wq,    wq_h,   wq_l,   (size_t)L_*D_*D_);
    run_split(wk,    wk_h,   wk_l,   (size_t)L_*D_*KVH_*HD_);
    run_split(wv,    wv_h,   wv_l,   (size_t)L_*D_*KVH_*HD_);
    run_split(wo,    wo_h,   wo_l,   (size_t)L_*D_*D_);
    run_split(wgate, wg_h,   wg_l,   (size_t)L_*D_*F_);
    run_split(wup,   wu_h,   wu_l,   (size_t)L_*D_*F_);
    run_split(wdown, wd_h,   wd_l,   (size_t)L_*F_*D_);
    run_split(wout,  wout_h, wout_l, (size_t)D_*V_);

    detect_idx_kernel<<<1, 256>>>((const int*)idx);
    embed_kernel<<<T_, 256>>>(idx, emb);

    for (int l = 0; l < L_; l++) {
        size_t oD  = (size_t)l * D_ * D_;
        size_t oKV = (size_t)l * D_ * KVH_ * HD_;
        size_t oF  = (size_t)l * D_ * F_;
        rmsnorm_split_kernel<<<T_, 256>>>(x, na + (size_t)l * D_, nh, nl);
        run_bgemm(nh, nl, wq_h + oD,  wq_l + oD,  nullptr, q, T_, D_,       D_);
        run_bgemm(nh, nl, wk_h + oKV, wk_l + oKV, nullptr, k, T_, KVH_*HD_, D_);
        run_bgemm(nh, nl, wv_h + oKV, wv_l + oKV, nullptr, v, T_, KVH_*HD_, D_);
        rope_split_kernel<<<T_, H_ * 32>>>(q, qh, ql, H_, SCALE_);
        rope_split_kernel<<<T_, KVH_ * 32>>>(k, kh, kl, KVH_, 1.0f);
        run_split(v, vh, vl, (size_t)T_*KVH_*HD_);
        flash_tc_kernel<<<dim3(S_/64, H_, B_), 128, FL_SMEM>>>(qh,ql,kh,kl,vh,vl,ch,cl);
        run_bgemm(ch, cl, wo_h + oD, wo_l + oD, x, x, T_, D_, D_);
        rmsnorm_split_kernel<<<T_, 256>>>(x, nf + (size_t)l * D_, nh, nl);
        run_bgemm(nh, nl, wg_h + oF, wg_l + oF, nullptr, gate, T_, F_, D_);
        run_bgemm(nh, nl, wu_h + oF, wu_l + oF, nullptr, up,   T_, F_, D_);
        silu_split_kernel<<<(T_ * F_ / 4) / 256, 256>>>(gate, up, gh, gl);
        run_bgemm(gh, gl, wd_h + (size_t)l*F_*D_, wd_l + (size_t)l*F_*D_,
                  x, x, T_, D_, F_);
    }

    rmsnorm_split_kernel<<<T_, 256>>>(x, nfin, nh, nl);
    run_bgemm(nh, nl, wout_h, wout_l, nullptr, (float*)d_out, T_, V_, D_);
}